// round 6
// baseline (speedup 1.0000x reference)
#include <cuda_runtime.h>
#include <cstdint>

// ---------------------------------------------------------------------------
// ShiftWindowMSA (Swin-V2): B=8, H=W=128, C=256, heads=8, hd=32, ws=8, ss=4
// Round 4: round-3 design with the LDS.128 alignment bug fixed
// (K tile padded to 36 floats/row = 144 B, 16B-aligned rows).
// ---------------------------------------------------------------------------

constexpr int CC    = 256;
constexpr int HEADS = 8;
constexpr int HD    = 32;
constexpr int SH    = 4;
constexpr int NTOK  = 64;
constexpr int BWIN  = 2048;

__device__ float g_q[BWIN * HEADS * NTOK * HD];
__device__ float g_k[BWIN * HEADS * NTOK * HD];
__device__ float g_v[BWIN * HEADS * NTOK * HD];
__device__ float g_ao[BWIN * NTOK * CC];
__device__ float g_bt[225 * 8];
__device__ float g_bias[HEADS * NTOK * NTOK];   // [h][m(key)][n(query)]

// ---------------------------------------------------------------------------
__device__ __forceinline__ uint32_t f2tf32(float f) {
    uint32_t r;
    asm("cvt.rna.tf32.f32 %0, %1;" : "=r"(r) : "f"(f));
    return r;
}
__device__ __forceinline__ uint4 cvt4(float4 f) {
    uint4 u;
    u.x = f2tf32(f.x); u.y = f2tf32(f.y); u.z = f2tf32(f.z); u.w = f2tf32(f.w);
    return u;
}
__device__ __forceinline__ void mma_tf32(float* d, const uint32_t* a,
                                         const uint32_t* b, const float* c) {
    asm("mma.sync.aligned.m16n8k8.row.col.f32.tf32.tf32.f32 "
        "{%0,%1,%2,%3}, {%4,%5,%6,%7}, {%8,%9}, {%10,%11,%12,%13};"
        : "=f"(d[0]), "=f"(d[1]), "=f"(d[2]), "=f"(d[3])
        : "r"(a[0]), "r"(a[1]), "r"(a[2]), "r"(a[3]),
          "r"(b[0]), "r"(b[1]),
          "f"(c[0]), "f"(c[1]), "f"(c[2]), "f"(c[3]));
}

// ---------------------------------------------------------------------------
// CPB MLP
// ---------------------------------------------------------------------------
__device__ __forceinline__ float cpb_coord(int i) {
    float c = (float)(i - 7) * (8.0f / 7.0f);
    float a = log2f(fabsf(c) + 1.0f) * (1.0f / 3.0f);
    return (c < 0.0f) ? -a : a;
}

__global__ void cpb_stage1(const float* __restrict__ w1, const float* __restrict__ b1,
                           const float* __restrict__ w2) {
    int idx = blockIdx.x * blockDim.x + threadIdx.x;
    if (idx >= 225 * 8) return;
    int t = idx >> 3, h = idx & 7;
    float t0 = cpb_coord(t / 15);
    float t1 = cpb_coord(t % 15);
    const float* w2h = w2 + h * 512;
    float acc = 0.0f;
    for (int o = 0; o < 512; o++) {
        float hid = fmaxf(fmaf(t0, w1[2 * o], fmaf(t1, w1[2 * o + 1], b1[o])), 0.0f);
        acc = fmaf(hid, w2h[o], acc);
    }
    g_bt[idx] = acc;
}

__global__ void cpb_stage2() {
    int idx = blockIdx.x * blockDim.x + threadIdx.x;
    int h = idx >> 12, rest = idx & 4095, m = rest >> 6, n = rest & 63;
    int dy = (n >> 3) - (m >> 3) + 7;
    int dx = (n & 7) - (m & 7) + 7;
    float b = g_bt[(dy * 15 + dx) * 8 + h];
    g_bias[idx] = 16.0f / (1.0f + __expf(-b));
}

// ---------------------------------------------------------------------------
// QKV GEMM (tf32): M=131072 gathered, N=768, K=256. 128x64 tile, BK=32.
// grid = (12, 1024), block = 256.
// ---------------------------------------------------------------------------
__global__ __launch_bounds__(256) void qkv_gemm_tc(
    const float* __restrict__ x, const float* __restrict__ w,
    const float* __restrict__ qb, const float* __restrict__ vb) {
    __shared__ uint32_t As[128][36];
    __shared__ uint32_t Bs[64][36];
    __shared__ int rowOff[128];

    const int tid = threadIdx.x;
    const int mb  = blockIdx.y;
    const int jt  = blockIdx.x;

    if (tid < 128) {
        int gm = (mb << 7) + tid;
        int win = gm >> 6, n = gm & 63;
        int b = win >> 8, wloc = win & 255, wy = wloc >> 4, wx = wloc & 15;
        int ly = n >> 3, lx = n & 7;
        int hs  = ((wy << 3) + ly + SH) & 127;
        int ws_ = ((wx << 3) + lx + SH) & 127;
        rowOff[tid] = ((((b << 7) + hs) << 7) | ws_) << 8;
    }
    __syncthreads();

    const int lane  = tid & 31, warp = tid >> 5;
    const int warpM = warp & 3, warpN = warp >> 2;
    const int la_row = tid >> 1;           // 0..127
    const int la_seg = (tid & 1) << 4;     // 0 / 16
    const int lb_row = tid >> 2;           // 0..63 (n)
    const int lb_seg = (tid & 3) << 3;     // 0,8,16,24 (k)
    const float* wRow = w + ((jt << 6) + lb_row) * 256;

    float acc[2][4][4] = {};

    for (int k0 = 0; k0 < 256; k0 += 32) {
        {
            const float* ap = x + rowOff[la_row] + k0 + la_seg;
#pragma unroll
            for (int v4 = 0; v4 < 4; v4++)
                *reinterpret_cast<uint4*>(&As[la_row][la_seg + v4 * 4]) =
                    cvt4(*reinterpret_cast<const float4*>(ap + v4 * 4));
        }
        {
            const float* bp = wRow + k0 + lb_seg;
            *reinterpret_cast<uint4*>(&Bs[lb_row][lb_seg]) =
                cvt4(*reinterpret_cast<const float4*>(bp));
            *reinterpret_cast<uint4*>(&Bs[lb_row][lb_seg + 4]) =
                cvt4(*reinterpret_cast<const float4*>(bp + 4));
        }
        __syncthreads();

#pragma unroll
        for (int ksb = 0; ksb < 4; ksb++) {
            uint32_t a[2][4], b[4][2];
            const int kc = (ksb << 3) + (lane & 3);
#pragma unroll
            for (int mf = 0; mf < 2; mf++) {
                int r = (warpM << 5) + (mf << 4) + (lane >> 2);
                a[mf][0] = As[r][kc];     a[mf][1] = As[r + 8][kc];
                a[mf][2] = As[r][kc + 4]; a[mf][3] = As[r + 8][kc + 4];
            }
#pragma unroll
            for (int nf = 0; nf < 4; nf++) {
                int n = (warpN << 5) + (nf << 3) + (lane >> 2);
                b[nf][0] = Bs[n][kc];
                b[nf][1] = Bs[n][kc + 4];
            }
#pragma unroll
            for (int mf = 0; mf < 2; mf++)
#pragma unroll
                for (int nf = 0; nf < 4; nf++)
                    mma_tf32(acc[mf][nf], a[mf], b[nf], acc[mf][nf]);
        }
        __syncthreads();
    }

    const int sel = jt >> 2;   // 0:q 1:k 2:v
    float* dstBase = (sel == 0) ? g_q : ((sel == 1) ? g_k : g_v);
#pragma unroll
    for (int nf = 0; nf < 4; nf++) {
        int jg = (jt << 6) + (warpN << 5) + (nf << 3) + ((lane & 3) << 1);
        float2 bias = make_float2(0.0f, 0.0f);
        if (sel == 0)      bias = make_float2(qb[jg], qb[jg + 1]);
        else if (sel == 2) bias = make_float2(vb[jg - 512], vb[jg - 511]);
        int head = (jg >> 5) & 7, d = jg & 31;
#pragma unroll
        for (int mf = 0; mf < 2; mf++) {
#pragma unroll
            for (int half = 0; half < 2; half++) {
                int r  = (warpM << 5) + (mf << 4) + (lane >> 2) + half * 8;
                int gm = (mb << 7) + r;
                int win = gm >> 6, n = gm & 63;
                float2 val = make_float2(acc[mf][nf][half * 2 + 0] + bias.x,
                                         acc[mf][nf][half * 2 + 1] + bias.y);
                float* dst = dstBase + ((size_t)(((win << 3) + head) << 6 | n) << 5) + d;
                *reinterpret_cast<float2*>(dst) = val;
            }
        }
    }
}

// ---------------------------------------------------------------------------
// Attention: 2 (win,head) pairs / 128-thread block; one query row per thread.
// K in smem (rows padded to 36 floats = 144 B, so LDS.128 stays aligned),
// V streamed from L1, single-pass softmax, bitmask shift mask.
// grid = 8192, block = 128.
// ---------------------------------------------------------------------------
__device__ __forceinline__ int region9(int wy, int wx, int n) {
    int rh = (wy == 15) ? (((n >> 3) < 4) ? 1 : 2) : 0;
    int rw = (wx == 15) ? (((n & 7) < 4) ? 1 : 2) : 0;
    return rh * 3 + rw;
}

__global__ __launch_bounds__(128) void attn_kernel(const float* __restrict__ ls) {
    __shared__ float ks[2][64][36];   // 36: 16B-aligned rows for LDS.128
    const int tid = threadIdx.x;
    const int sub = tid >> 6;
    const int t   = tid & 63;
    const int pair = (blockIdx.x << 1) + sub;
    const int win = pair >> 3, h = pair & 7;

    // stage K (vectorized; row stride 144 B keeps STS.128 aligned)
    {
        const float4* kp = reinterpret_cast<const float4*>(
            g_k + (size_t)pair * (NTOK * HD));
#pragma unroll
        for (int i = t; i < NTOK * HD / 4; i += 64) {
            float4 f = kp[i];
            *reinterpret_cast<float4*>(&ks[sub][i >> 3][(i & 7) << 2]) = f;
        }
    }
    __syncthreads();

    // normalize own K row (in place)
    {
        float s = 0.0f;
#pragma unroll
        for (int d = 0; d < 32; d++) { float x = ks[sub][t][d]; s = fmaf(x, x, s); }
        float inv = rsqrtf(fmaxf(s, 1e-24f));
#pragma unroll
        for (int d = 0; d < 32; d++) ks[sub][t][d] *= inv;
    }

    // own Q row, normalized and pre-scaled
    float q[32];
    float scale = __expf(fminf(ls[h], 4.6051702f));
    {
        const float4* qp = reinterpret_cast<const float4*>(
            g_q + ((size_t)pair * NTOK + t) * HD);
        float s = 0.0f;
#pragma unroll
        for (int d4 = 0; d4 < 8; d4++) {
            float4 f = qp[d4];
            q[d4 * 4 + 0] = f.x; q[d4 * 4 + 1] = f.y;
            q[d4 * 4 + 2] = f.z; q[d4 * 4 + 3] = f.w;
            s = fmaf(f.x, f.x, fmaf(f.y, f.y, fmaf(f.z, f.z, fmaf(f.w, f.w, s))));
        }
        float inv = rsqrtf(fmaxf(s, 1e-24f)) * scale;
#pragma unroll
        for (int d = 0; d < 32; d++) q[d] *= inv;
    }
    __syncthreads();

    // shift mask bitmask (nonzero only for boundary windows)
    const int wloc = win & 255, wy = wloc >> 4, wx = wloc & 15;
    uint32_t mlo = 0, mhi = 0;
    if (wy == 15 || wx == 15) {
        const int rn = region9(wy, wx, t);
        for (int m = 0; m < 64; m++)
            if (region9(wy, wx, m) != rn) {
                if (m < 32) mlo |= (1u << m); else mhi |= (1u << (m - 32));
            }
    }

    const float* biasT = g_bias + (h << 12) + t;   // [h][m][n]: +64 per m
    const float4* vp = reinterpret_cast<const float4*>(g_v + (size_t)pair * (NTOK * HD));
    const float mx = scale + 16.0f;

    float sum = 0.0f;
    float out[32] = {};
#pragma unroll 4
    for (int m = 0; m < 64; m++) {
        float dot = 0.0f;
#pragma unroll
        for (int d4 = 0; d4 < 8; d4++) {
            float4 kk = *reinterpret_cast<const float4*>(&ks[sub][m][d4 * 4]);
            dot = fmaf(q[d4 * 4 + 0], kk.x, dot);
            dot = fmaf(q[d4 * 4 + 1], kk.y, dot);
            dot = fmaf(q[d4 * 4 + 2], kk.z, dot);
            dot = fmaf(q[d4 * 4 + 3], kk.w, dot);
        }
        uint32_t bit = (m < 32) ? ((mlo >> m) & 1u) : ((mhi >> (m - 32)) & 1u);
        float v = dot + __ldg(&biasT[m << 6]) + (bit ? -100.0f : 0.0f);
        float e = __expf(v - mx);
        sum += e;
#pragma unroll
        for (int d4 = 0; d4 < 8; d4++) {
            float4 vv = __ldg(&vp[m * 8 + d4]);
            out[d4 * 4 + 0] = fmaf(e, vv.x, out[d4 * 4 + 0]);
            out[d4 * 4 + 1] = fmaf(e, vv.y, out[d4 * 4 + 1]);
            out[d4 * 4 + 2] = fmaf(e, vv.z, out[d4 * 4 + 2]);
            out[d4 * 4 + 3] = fmaf(e, vv.w, out[d4 * 4 + 3]);
        }
    }
    float rinv = 1.0f / sum;

    float* op = g_ao + ((size_t)(win << 6) + t) * CC + (h << 5);
#pragma unroll
    for (int d = 0; d < 32; d += 4) {
        float4 v4 = make_float4(out[d] * rinv, out[d + 1] * rinv,
                                out[d + 2] * rinv, out[d + 3] * rinv);
        *reinterpret_cast<float4*>(op + d) = v4;
    }
}

// ---------------------------------------------------------------------------
// Projection GEMM (tf32): M=131072, N=256, K=256; fused window-reverse +
// unshift scatter. grid = (4, 1024), block = 256.
// ---------------------------------------------------------------------------
__global__ __launch_bounds__(256) void proj_gemm_tc(
    const float* __restrict__ w, const float* __restrict__ pb,
    float* __restrict__ out) {
    __shared__ uint32_t As[128][36];
    __shared__ uint32_t Bs[64][36];

    const int tid = threadIdx.x;
    const int mb  = blockIdx.y;
    const int jt  = blockIdx.x;

    const int lane  = tid & 31, warp = tid >> 5;
    const int warpM = warp & 3, warpN = warp >> 2;
    const int la_row = tid >> 1;
    const int la_seg = (tid & 1) << 4;
    const int lb_row = tid >> 2;
    const int lb_seg = (tid & 3) << 3;
    const float* aRow = g_ao + (size_t)((mb << 7) + la_row) * 256;
    const float* wRow = w + ((jt << 6) + lb_row) * 256;

    float acc[2][4][4] = {};

    for (int k0 = 0; k0 < 256; k0 += 32) {
        {
            const float* ap = aRow + k0 + la_seg;
#pragma unroll
            for (int v4 = 0; v4 < 4; v4++)
                *reinterpret_cast<uint4*>(&As[la_row][la_seg + v4 * 4]) =
                    cvt4(*reinterpret_cast<const float4*>(ap + v4 * 4));
        }
        {
            const float* bp = wRow + k0 + lb_seg;
            *reinterpret_cast<uint4*>(&Bs[lb_row][lb_seg]) =
                cvt4(*reinterpret_cast<const float4*>(bp));
            *reinterpret_cast<uint4*>(&Bs[lb_row][lb_seg + 4]) =
                cvt4(*reinterpret_cast<const float4*>(bp + 4));
        }
        __syncthreads();

#pragma unroll
        for (int ksb = 0; ksb < 4; ksb++) {
            uint32_t a[2][4], b[4][2];
            const int kc = (ksb << 3) + (lane & 3);
#pragma unroll
            for (int mf = 0; mf < 2; mf++) {
                int r = (warpM << 5) + (mf << 4) + (lane >> 2);
                a[mf][0] = As[r][kc];     a[mf][1] = As[r + 8][kc];
                a[mf][2] = As[r][kc + 4]; a[mf][3] = As[r + 8][kc + 4];
            }
#pragma unroll
            for (int nf = 0; nf < 4; nf++) {
                int n = (warpN << 5) + (nf << 3) + (lane >> 2);
                b[nf][0] = Bs[n][kc];
                b[nf][1] = Bs[n][kc + 4];
            }
#pragma unroll
            for (int mf = 0; mf < 2; mf++)
#pragma unroll
                for (int nf = 0; nf < 4; nf++)
                    mma_tf32(acc[mf][nf], a[mf], b[nf], acc[mf][nf]);
        }
        __syncthreads();
    }

#pragma unroll
    for (int nf = 0; nf < 4; nf++) {
        int jg = (jt << 6) + (warpN << 5) + (nf << 3) + ((lane & 3) << 1);
        float2 bias = make_float2(pb[jg], pb[jg + 1]);
#pragma unroll
        for (int mf = 0; mf < 2; mf++) {
#pragma unroll
            for (int half = 0; half < 2; half++) {
                int r  = (warpM << 5) + (mf << 4) + (lane >> 2) + half * 8;
                int gm = (mb << 7) + r;
                int win = gm >> 6, n = gm & 63;
                int b = win >> 8, wloc = win & 255, wy = wloc >> 4, wx = wloc & 15;
                int ly = n >> 3, lx = n & 7;
                int hd_ = ((wy << 3) + ly + SH) & 127;
                int wd_ = ((wx << 3) + lx + SH) & 127;
                size_t rowoff = ((size_t)((((b << 7) + hd_) << 7) | wd_)) << 8;
                float2 val = make_float2(acc[mf][nf][half * 2 + 0] + bias.x,
                                         acc[mf][nf][half * 2 + 1] + bias.y);
                *reinterpret_cast<float2*>(out + rowoff + jg) = val;
            }
        }
    }
}

// ---------------------------------------------------------------------------
extern "C" void kernel_launch(void* const* d_in, const int* in_sizes, int n_in,
                              void* d_out, int out_size) {
    const float* x      = (const float*)d_in[0];
    const float* qkv_w  = (const float*)d_in[1];
    const float* q_bias = (const float*)d_in[2];
    const float* v_bias = (const float*)d_in[3];
    const float* lscale = (const float*)d_in[4];
    const float* cpb_w1 = (const float*)d_in[5];
    const float* cpb_b1 = (const float*)d_in[6];
    const float* cpb_w2 = (const float*)d_in[7];
    const float* proj_w = (const float*)d_in[8];
    const float* proj_b = (const float*)d_in[9];
    float* out = (float*)d_out;

    cpb_stage1<<<8, 256>>>(cpb_w1, cpb_b1, cpb_w2);
    cpb_stage2<<<128, 256>>>();
    qkv_gemm_tc<<<dim3(12, 1024), 256>>>(x, qkv_w, q_bias, v_bias);
    attn_kernel<<<8192, 128>>>(lscale);
    proj_gemm_tc<<<dim3(4, 1024), 256>>>(proj_w, proj_b, out);
}

// round 7
// speedup vs baseline: 1.1504x; 1.1504x over previous
#include <cuda_runtime.h>
#include <cstdint>

// ---------------------------------------------------------------------------
// ShiftWindowMSA (Swin-V2): B=8, H=W=128, C=256, heads=8, hd=32, ws=8, ss=4
// Round 7: double-buffered tf32 GEMMs (1 barrier/k-iter, prefetch overlap),
// attention with split dot accumulators (ILP) and K+V both in smem.
// ---------------------------------------------------------------------------

constexpr int CC    = 256;
constexpr int HEADS = 8;
constexpr int HD    = 32;
constexpr int SH    = 4;
constexpr int NTOK  = 64;
constexpr int BWIN  = 2048;

// dyn smem layout words
constexpr int A_WORDS = 128 * 36;            // 4608
constexpr int B_WORDS = 64 * 36;             // 2304
constexpr int STAGE_WORDS = A_WORDS + B_WORDS;   // 6912
constexpr int QKV_SMEM_BYTES  = (2 * STAGE_WORDS + 128) * 4;  // +rowOff
constexpr int PROJ_SMEM_BYTES = (2 * STAGE_WORDS) * 4;

__device__ float g_q[BWIN * HEADS * NTOK * HD];
__device__ float g_k[BWIN * HEADS * NTOK * HD];
__device__ float g_v[BWIN * HEADS * NTOK * HD];
__device__ float g_ao[BWIN * NTOK * CC];
__device__ float g_bt[225 * 8];
__device__ float g_bias[HEADS * NTOK * NTOK];   // [h][m(key)][n(query)]

// ---------------------------------------------------------------------------
__device__ __forceinline__ uint32_t f2tf32(float f) {
    uint32_t r;
    asm("cvt.rna.tf32.f32 %0, %1;" : "=r"(r) : "f"(f));
    return r;
}
__device__ __forceinline__ uint4 cvt4(float4 f) {
    uint4 u;
    u.x = f2tf32(f.x); u.y = f2tf32(f.y); u.z = f2tf32(f.z); u.w = f2tf32(f.w);
    return u;
}
__device__ __forceinline__ void mma_tf32(float* d, const uint32_t* a,
                                         const uint32_t* b, const float* c) {
    asm("mma.sync.aligned.m16n8k8.row.col.f32.tf32.tf32.f32 "
        "{%0,%1,%2,%3}, {%4,%5,%6,%7}, {%8,%9}, {%10,%11,%12,%13};"
        : "=f"(d[0]), "=f"(d[1]), "=f"(d[2]), "=f"(d[3])
        : "r"(a[0]), "r"(a[1]), "r"(a[2]), "r"(a[3]),
          "r"(b[0]), "r"(b[1]),
          "f"(c[0]), "f"(c[1]), "f"(c[2]), "f"(c[3]));
}

// ---------------------------------------------------------------------------
// CPB MLP
// ---------------------------------------------------------------------------
__device__ __forceinline__ float cpb_coord(int i) {
    float c = (float)(i - 7) * (8.0f / 7.0f);
    float a = log2f(fabsf(c) + 1.0f) * (1.0f / 3.0f);
    return (c < 0.0f) ? -a : a;
}

__global__ void cpb_stage1(const float* __restrict__ w1, const float* __restrict__ b1,
                           const float* __restrict__ w2) {
    int idx = blockIdx.x * blockDim.x + threadIdx.x;
    if (idx >= 225 * 8) return;
    int t = idx >> 3, h = idx & 7;
    float t0 = cpb_coord(t / 15);
    float t1 = cpb_coord(t % 15);
    const float* w2h = w2 + h * 512;
    float acc = 0.0f;
    for (int o = 0; o < 512; o++) {
        float hid = fmaxf(fmaf(t0, w1[2 * o], fmaf(t1, w1[2 * o + 1], b1[o])), 0.0f);
        acc = fmaf(hid, w2h[o], acc);
    }
    g_bt[idx] = acc;
}

__global__ void cpb_stage2() {
    int idx = blockIdx.x * blockDim.x + threadIdx.x;
    int h = idx >> 12, rest = idx & 4095, m = rest >> 6, n = rest & 63;
    int dy = (n >> 3) - (m >> 3) + 7;
    int dx = (n & 7) - (m & 7) + 7;
    float b = g_bt[(dy * 15 + dx) * 8 + h];
    g_bias[idx] = 16.0f / (1.0f + __expf(-b));
}

// ---------------------------------------------------------------------------
// QKV GEMM (tf32, double-buffered): M=131072 gathered, N=768, K=256.
// 128x64 tile, BK=32. grid = (12, 1024), block = 256, dyn smem 55.8 KB.
// ---------------------------------------------------------------------------
__global__ __launch_bounds__(256) void qkv_gemm_tc(
    const float* __restrict__ x, const float* __restrict__ w,
    const float* __restrict__ qb, const float* __restrict__ vb) {
    extern __shared__ uint32_t dyn[];
    int* rowOff = (int*)(dyn + 2 * STAGE_WORDS);

    const int tid = threadIdx.x;
    const int mb  = blockIdx.y;
    const int jt  = blockIdx.x;

    if (tid < 128) {
        int gm = (mb << 7) + tid;
        int win = gm >> 6, n = gm & 63;
        int b = win >> 8, wloc = win & 255, wy = wloc >> 4, wx = wloc & 15;
        int ly = n >> 3, lx = n & 7;
        int hs  = ((wy << 3) + ly + SH) & 127;
        int ws_ = ((wx << 3) + lx + SH) & 127;
        rowOff[tid] = ((((b << 7) + hs) << 7) | ws_) << 8;
    }
    __syncthreads();

    const int lane  = tid & 31, warp = tid >> 5;
    const int warpM = warp & 3, warpN = warp >> 2;
    const int la_row = tid >> 1;           // 0..127
    const int la_seg = (tid & 1) << 4;     // 0 / 16
    const int lb_row = tid >> 2;           // 0..63 (n)
    const int lb_seg = (tid & 3) << 3;     // 0,8,16,24 (k)
    const float* xRow = x + rowOff[la_row];
    const float* wRow = w + ((jt << 6) + lb_row) * 256;

    float acc[2][4][4] = {};
    float4 pa[4], pb[2];

    auto loadg = [&](int k0) {
        const float* ap = xRow + k0 + la_seg;
#pragma unroll
        for (int v = 0; v < 4; v++)
            pa[v] = *reinterpret_cast<const float4*>(ap + v * 4);
        const float* bp = wRow + k0 + lb_seg;
        pb[0] = *reinterpret_cast<const float4*>(bp);
        pb[1] = *reinterpret_cast<const float4*>(bp + 4);
    };
    auto stores = [&](int s) {
        uint32_t* A = dyn + s * STAGE_WORDS;
        uint32_t* B = A + A_WORDS;
#pragma unroll
        for (int v = 0; v < 4; v++)
            *reinterpret_cast<uint4*>(&A[la_row * 36 + la_seg + v * 4]) = cvt4(pa[v]);
        *reinterpret_cast<uint4*>(&B[lb_row * 36 + lb_seg])     = cvt4(pb[0]);
        *reinterpret_cast<uint4*>(&B[lb_row * 36 + lb_seg + 4]) = cvt4(pb[1]);
    };
    auto compute = [&](int s) {
        const uint32_t* A = dyn + s * STAGE_WORDS;
        const uint32_t* B = A + A_WORDS;
#pragma unroll
        for (int ksb = 0; ksb < 4; ksb++) {
            uint32_t a[2][4], b[4][2];
            const int kc = (ksb << 3) + (lane & 3);
#pragma unroll
            for (int mf = 0; mf < 2; mf++) {
                int r = (warpM << 5) + (mf << 4) + (lane >> 2);
                a[mf][0] = A[r * 36 + kc];       a[mf][1] = A[(r + 8) * 36 + kc];
                a[mf][2] = A[r * 36 + kc + 4];   a[mf][3] = A[(r + 8) * 36 + kc + 4];
            }
#pragma unroll
            for (int nf = 0; nf < 4; nf++) {
                int n = (warpN << 5) + (nf << 3) + (lane >> 2);
                b[nf][0] = B[n * 36 + kc];
                b[nf][1] = B[n * 36 + kc + 4];
            }
#pragma unroll
            for (int mf = 0; mf < 2; mf++)
#pragma unroll
                for (int nf = 0; nf < 4; nf++)
                    mma_tf32(acc[mf][nf], a[mf], b[nf], acc[mf][nf]);
        }
    };

    loadg(0);
    stores(0);
    __syncthreads();
#pragma unroll
    for (int it = 0; it < 8; it++) {
        if (it < 7) loadg((it + 1) << 5);
        compute(it & 1);
        if (it < 7) {
            stores((it + 1) & 1);
            __syncthreads();
        }
    }

    const int sel = jt >> 2;   // 0:q 1:k 2:v
    float* dstBase = (sel == 0) ? g_q : ((sel == 1) ? g_k : g_v);
#pragma unroll
    for (int nf = 0; nf < 4; nf++) {
        int jg = (jt << 6) + (warpN << 5) + (nf << 3) + ((lane & 3) << 1);
        float2 bias = make_float2(0.0f, 0.0f);
        if (sel == 0)      bias = make_float2(qb[jg], qb[jg + 1]);
        else if (sel == 2) bias = make_float2(vb[jg - 512], vb[jg - 511]);
        int head = (jg >> 5) & 7, d = jg & 31;
#pragma unroll
        for (int mf = 0; mf < 2; mf++) {
#pragma unroll
            for (int half = 0; half < 2; half++) {
                int r  = (warpM << 5) + (mf << 4) + (lane >> 2) + half * 8;
                int gm = (mb << 7) + r;
                int win = gm >> 6, n = gm & 63;
                float2 val = make_float2(acc[mf][nf][half * 2 + 0] + bias.x,
                                         acc[mf][nf][half * 2 + 1] + bias.y);
                float* dst = dstBase + ((size_t)(((win << 3) + head) << 6 | n) << 5) + d;
                *reinterpret_cast<float2*>(dst) = val;
            }
        }
    }
}

// ---------------------------------------------------------------------------
// Attention: 2 (win,head) pairs / 128-thread block; one query row per thread.
// K+V in smem (broadcast LDS), 4-way split dot accumulators for ILP,
// single-pass softmax (mx = scale+16 bound), bitmask shift mask.
// grid = 8192, block = 128.
// ---------------------------------------------------------------------------
__device__ __forceinline__ int region9(int wy, int wx, int n) {
    int rh = (wy == 15) ? (((n >> 3) < 4) ? 1 : 2) : 0;
    int rw = (wx == 15) ? (((n & 7) < 4) ? 1 : 2) : 0;
    return rh * 3 + rw;
}

__global__ __launch_bounds__(128) void attn_kernel(const float* __restrict__ ls) {
    __shared__ float ks[2][64][36];
    __shared__ float vs[2][64][36];
    const int tid = threadIdx.x;
    const int sub = tid >> 6;
    const int t   = tid & 63;
    const int pair = (blockIdx.x << 1) + sub;
    const int win = pair >> 3, h = pair & 7;

    // stage K and V (row stride 144 B keeps STS.128 aligned)
    {
        const float4* kp = reinterpret_cast<const float4*>(
            g_k + (size_t)pair * (NTOK * HD));
        const float4* vp = reinterpret_cast<const float4*>(
            g_v + (size_t)pair * (NTOK * HD));
#pragma unroll
        for (int i = t; i < NTOK * HD / 4; i += 64) {
            *reinterpret_cast<float4*>(&ks[sub][i >> 3][(i & 7) << 2]) = kp[i];
            *reinterpret_cast<float4*>(&vs[sub][i >> 3][(i & 7) << 2]) = vp[i];
        }
    }
    __syncthreads();

    // normalize own K row (in place)
    {
        float s0 = 0.0f, s1 = 0.0f, s2 = 0.0f, s3 = 0.0f;
#pragma unroll
        for (int d = 0; d < 32; d += 4) {
            s0 = fmaf(ks[sub][t][d],     ks[sub][t][d],     s0);
            s1 = fmaf(ks[sub][t][d + 1], ks[sub][t][d + 1], s1);
            s2 = fmaf(ks[sub][t][d + 2], ks[sub][t][d + 2], s2);
            s3 = fmaf(ks[sub][t][d + 3], ks[sub][t][d + 3], s3);
        }
        float inv = rsqrtf(fmaxf((s0 + s1) + (s2 + s3), 1e-24f));
#pragma unroll
        for (int d = 0; d < 32; d++) ks[sub][t][d] *= inv;
    }

    // own Q row, normalized and pre-scaled
    float q[32];
    float scale = __expf(fminf(ls[h], 4.6051702f));
    {
        const float4* qp = reinterpret_cast<const float4*>(
            g_q + ((size_t)pair * NTOK + t) * HD);
        float s0 = 0.0f, s1 = 0.0f, s2 = 0.0f, s3 = 0.0f;
#pragma unroll
        for (int d4 = 0; d4 < 8; d4++) {
            float4 f = qp[d4];
            q[d4 * 4 + 0] = f.x; q[d4 * 4 + 1] = f.y;
            q[d4 * 4 + 2] = f.z; q[d4 * 4 + 3] = f.w;
            s0 = fmaf(f.x, f.x, s0); s1 = fmaf(f.y, f.y, s1);
            s2 = fmaf(f.z, f.z, s2); s3 = fmaf(f.w, f.w, s3);
        }
        float inv = rsqrtf(fmaxf((s0 + s1) + (s2 + s3), 1e-24f)) * scale;
#pragma unroll
        for (int d = 0; d < 32; d++) q[d] *= inv;
    }
    __syncthreads();

    // shift mask bitmask (nonzero only for boundary windows)
    const int wloc = win & 255, wy = wloc >> 4, wx = wloc & 15;
    uint32_t mlo = 0, mhi = 0;
    if (wy == 15 || wx == 15) {
        const int rn = region9(wy, wx, t);
        for (int m = 0; m < 64; m++)
            if (region9(wy, wx, m) != rn) {
                if (m < 32) mlo |= (1u << m); else mhi |= (1u << (m - 32));
            }
    }

    const float* biasT = g_bias + (h << 12) + t;   // [h][m][n]: +64 per m
    const float mx = scale + 16.0f;

    float sum = 0.0f;
    float out[32] = {};
#pragma unroll 2
    for (int m = 0; m < 64; m++) {
        // dot with 4 independent accumulator chains (depth 8 each)
        float a0 = 0.0f, a1 = 0.0f, a2 = 0.0f, a3 = 0.0f;
#pragma unroll
        for (int d4 = 0; d4 < 8; d4++) {
            float4 kk = *reinterpret_cast<const float4*>(&ks[sub][m][d4 * 4]);
            a0 = fmaf(q[d4 * 4 + 0], kk.x, a0);
            a1 = fmaf(q[d4 * 4 + 1], kk.y, a1);
            a2 = fmaf(q[d4 * 4 + 2], kk.z, a2);
            a3 = fmaf(q[d4 * 4 + 3], kk.w, a3);
        }
        float dot = (a0 + a1) + (a2 + a3);
        uint32_t bit = (m < 32) ? ((mlo >> m) & 1u) : ((mhi >> (m - 32)) & 1u);
        float v = dot + __ldg(&biasT[m << 6]) + (bit ? -100.0f : 0.0f);
        float e = __expf(v - mx);
        sum += e;
#pragma unroll
        for (int d4 = 0; d4 < 8; d4++) {
            float4 vv = *reinterpret_cast<const float4*>(&vs[sub][m][d4 * 4]);
            out[d4 * 4 + 0] = fmaf(e, vv.x, out[d4 * 4 + 0]);
            out[d4 * 4 + 1] = fmaf(e, vv.y, out[d4 * 4 + 1]);
            out[d4 * 4 + 2] = fmaf(e, vv.z, out[d4 * 4 + 2]);
            out[d4 * 4 + 3] = fmaf(e, vv.w, out[d4 * 4 + 3]);
        }
    }
    float rinv = 1.0f / sum;

    float* op = g_ao + ((size_t)(win << 6) + t) * CC + (h << 5);
#pragma unroll
    for (int d = 0; d < 32; d += 4) {
        float4 v4 = make_float4(out[d] * rinv, out[d + 1] * rinv,
                                out[d + 2] * rinv, out[d + 3] * rinv);
        *reinterpret_cast<float4*>(op + d) = v4;
    }
}

// ---------------------------------------------------------------------------
// Projection GEMM (tf32, double-buffered): M=131072, N=256, K=256; fused
// window-reverse + unshift scatter. grid = (4, 1024), block = 256.
// ---------------------------------------------------------------------------
__global__ __launch_bounds__(256) void proj_gemm_tc(
    const float* __restrict__ w, const float* __restrict__ pb,
    float* __restrict__ out) {
    extern __shared__ uint32_t dyn[];

    const int tid = threadIdx.x;
    const int mb  = blockIdx.y;
    const int jt  = blockIdx.x;

    const int lane  = tid & 31, warp = tid >> 5;
    const int warpM = warp & 3, warpN = warp >> 2;
    const int la_row = tid >> 1;
    const int la_seg = (tid & 1) << 4;
    const int lb_row = tid >> 2;
    const int lb_seg = (tid & 3) << 3;
    const float* aRow = g_ao + (size_t)((mb << 7) + la_row) * 256;
    const float* wRow = w + ((jt << 6) + lb_row) * 256;

    float acc[2][4][4] = {};
    float4 pa[4], pbv[2];

    auto loadg = [&](int k0) {
        const float* ap = aRow + k0 + la_seg;
#pragma unroll
        for (int v = 0; v < 4; v++)
            pa[v] = *reinterpret_cast<const float4*>(ap + v * 4);
        const float* bp = wRow + k0 + lb_seg;
        pbv[0] = *reinterpret_cast<const float4*>(bp);
        pbv[1] = *reinterpret_cast<const float4*>(bp + 4);
    };
    auto stores = [&](int s) {
        uint32_t* A = dyn + s * STAGE_WORDS;
        uint32_t* B = A + A_WORDS;
#pragma unroll
        for (int v = 0; v < 4; v++)
            *reinterpret_cast<uint4*>(&A[la_row * 36 + la_seg + v * 4]) = cvt4(pa[v]);
        *reinterpret_cast<uint4*>(&B[lb_row * 36 + lb_seg])     = cvt4(pbv[0]);
        *reinterpret_cast<uint4*>(&B[lb_row * 36 + lb_seg + 4]) = cvt4(pbv[1]);
    };
    auto compute = [&](int s) {
        const uint32_t* A = dyn + s * STAGE_WORDS;
        const uint32_t* B = A + A_WORDS;
#pragma unroll
        for (int ksb = 0; ksb < 4; ksb++) {
            uint32_t a[2][4], b[4][2];
            const int kc = (ksb << 3) + (lane & 3);
#pragma unroll
            for (int mf = 0; mf < 2; mf++) {
                int r = (warpM << 5) + (mf << 4) + (lane >> 2);
                a[mf][0] = A[r * 36 + kc];       a[mf][1] = A[(r + 8) * 36 + kc];
                a[mf][2] = A[r * 36 + kc + 4];   a[mf][3] = A[(r + 8) * 36 + kc + 4];
            }
#pragma unroll
            for (int nf = 0; nf < 4; nf++) {
                int n = (warpN << 5) + (nf << 3) + (lane >> 2);
                b[nf][0] = B[n * 36 + kc];
                b[nf][1] = B[n * 36 + kc + 4];
            }
#pragma unroll
            for (int mf = 0; mf < 2; mf++)
#pragma unroll
                for (int nf = 0; nf < 4; nf++)
                    mma_tf32(acc[mf][nf], a[mf], b[nf], acc[mf][nf]);
        }
    };

    loadg(0);
    stores(0);
    __syncthreads();
#pragma unroll
    for (int it = 0; it < 8; it++) {
        if (it < 7) loadg((it + 1) << 5);
        compute(it & 1);
        if (it < 7) {
            stores((it + 1) & 1);
            __syncthreads();
        }
    }

#pragma unroll
    for (int nf = 0; nf < 4; nf++) {
        int jg = (jt << 6) + (warpN << 5) + (nf << 3) + ((lane & 3) << 1);
        float2 bias = make_float2(pb[jg], pb[jg + 1]);
#pragma unroll
        for (int mf = 0; mf < 2; mf++) {
#pragma unroll
            for (int half = 0; half < 2; half++) {
                int r  = (warpM << 5) + (mf << 4) + (lane >> 2) + half * 8;
                int gm = (mb << 7) + r;
                int win = gm >> 6, n = gm & 63;
                int b = win >> 8, wloc = win & 255, wy = wloc >> 4, wx = wloc & 15;
                int ly = n >> 3, lx = n & 7;
                int hd_ = ((wy << 3) + ly + SH) & 127;
                int wd_ = ((wx << 3) + lx + SH) & 127;
                size_t rowoff = ((size_t)((((b << 7) + hd_) << 7) | wd_)) << 8;
                float2 val = make_float2(acc[mf][nf][half * 2 + 0] + bias.x,
                                         acc[mf][nf][half * 2 + 1] + bias.y);
                *reinterpret_cast<float2*>(out + rowoff + jg) = val;
            }
        }
    }
}

// ---------------------------------------------------------------------------
extern "C" void kernel_launch(void* const* d_in, const int* in_sizes, int n_in,
                              void* d_out, int out_size) {
    const float* x      = (const float*)d_in[0];
    const float* qkv_w  = (const float*)d_in[1];
    const float* q_bias = (const float*)d_in[2];
    const float* v_bias = (const float*)d_in[3];
    const float* lscale = (const float*)d_in[4];
    const float* cpb_w1 = (const float*)d_in[5];
    const float* cpb_b1 = (const float*)d_in[6];
    const float* cpb_w2 = (const float*)d_in[7];
    const float* proj_w = (const float*)d_in[8];
    const float* proj_b = (const float*)d_in[9];
    float* out = (float*)d_out;

    cudaFuncSetAttribute(qkv_gemm_tc, cudaFuncAttributeMaxDynamicSharedMemorySize,
                         QKV_SMEM_BYTES);
    cudaFuncSetAttribute(proj_gemm_tc, cudaFuncAttributeMaxDynamicSharedMemorySize,
                         PROJ_SMEM_BYTES);

    cpb_stage1<<<8, 256>>>(cpb_w1, cpb_b1, cpb_w2);
    cpb_stage2<<<128, 256>>>();
    qkv_gemm_tc<<<dim3(12, 1024), 256, QKV_SMEM_BYTES>>>(x, qkv_w, q_bias, v_bias);
    attn_kernel<<<8192, 128>>>(lscale);
    proj_gemm_tc<<<dim3(4, 1024), 256, PROJ_SMEM_BYTES>>>(proj_w, proj_b, out);
}